// round 1
// baseline (speedup 1.0000x reference)
#include <cuda_runtime.h>
#include <cstdint>
#include <cstddef>

#define NROWS 16384
#define EPSV  1e-5f

// ---------------------------------------------------------------------------
// Scratch (device globals; no allocation allowed)
// ---------------------------------------------------------------------------
__device__ uint32_t g_xb  [NROWS * 24];    // binarized input  [16384][24]
__device__ uint32_t g_act0[NROWS * 128];   // packed activations ping
__device__ uint32_t g_act1[NROWS * 128];   // packed activations pong
__device__ uint32_t g_wb1 [4096 * 24];
__device__ uint32_t g_wb2 [4096 * 128];
__device__ uint32_t g_wb3 [4096 * 128];
__device__ uint32_t g_wb4 [16   * 128];

// ---------------------------------------------------------------------------
// Binarize: bit = (value < 0)  (so x>=0 -> +1 matches ste_sign, incl. -0.0)
// One warp per row; ballot packs 32 consecutive elements into one word.
// ---------------------------------------------------------------------------
__global__ void binarize_kernel(const float* __restrict__ src, uint32_t* __restrict__ dst,
                                int rows, int kwords, int stride) {
    int wg   = (blockIdx.x * blockDim.x + threadIdx.x) >> 5;
    int lane = threadIdx.x & 31;
    if (wg >= rows) return;
    const float* p = src + (size_t)wg * (size_t)stride;
    for (int w = 0; w < kwords; ++w) {
        unsigned bits = __ballot_sync(0xffffffffu, p[w * 32 + lane] < 0.0f);
        if (lane == 0) dst[(size_t)wg * kwords + w] = bits;
    }
}

// ---------------------------------------------------------------------------
// Bit-GEMM + BN-threshold + repack.
// Tile: BM=128 rows x BN=64 cols per CTA, 256 threads, 8x4 outputs/thread.
// K processed in chunks of KCH words through static shared memory.
// h = Kfull - 2*popc_sum  (exact integer);  f = (h+b - m)*(g*rsqrt(v+eps)) + be
// computed with non-contracted fp32 ops to bit-match XLA; output bit = (f<0).
// ---------------------------------------------------------------------------
template<int KW, int KCH>
__global__ void __launch_bounds__(256) bitgemm_kernel(
        const uint32_t* __restrict__ A, const uint32_t* __restrict__ W,
        const float* __restrict__ bias, const float* __restrict__ gam,
        const float* __restrict__ bet,  const float* __restrict__ mean,
        const float* __restrict__ var,  uint32_t* __restrict__ O, int Kfull) {
    __shared__ uint32_t As[128][KCH + 1];
    __shared__ uint32_t Ws[64][KCH + 1];

    const int tid     = threadIdx.x;
    const int rowBase = blockIdx.y * 128;
    const int colBase = blockIdx.x * 64;
    const int tx = tid & 15;   // -> 4 cols
    const int ty = tid >> 4;   // -> 8 rows

    uint32_t acc[8][4];
#pragma unroll
    for (int i = 0; i < 8; ++i)
#pragma unroll
        for (int j = 0; j < 4; ++j) acc[i][j] = 0u;

    for (int kb = 0; kb < KW; kb += KCH) {
        for (int idx = tid; idx < 128 * KCH; idx += 256) {
            int r = idx / KCH, k = idx - r * KCH;
            As[r][k] = A[(size_t)(rowBase + r) * KW + kb + k];
        }
        for (int idx = tid; idx < 64 * KCH; idx += 256) {
            int r = idx / KCH, k = idx - r * KCH;
            Ws[r][k] = W[(size_t)(colBase + r) * KW + kb + k];
        }
        __syncthreads();

#pragma unroll 4
        for (int k = 0; k < KCH; ++k) {
            uint32_t aw[8], ww[4];
#pragma unroll
            for (int i = 0; i < 8; ++i) aw[i] = As[ty * 8 + i][k];
#pragma unroll
            for (int j = 0; j < 4; ++j) ww[j] = Ws[tx * 4 + j][k];
#pragma unroll
            for (int i = 0; i < 8; ++i)
#pragma unroll
                for (int j = 0; j < 4; ++j)
                    acc[i][j] += (uint32_t)__popc(aw[i] ^ ww[j]);
        }
        __syncthreads();
    }

    // Epilogue: BN threshold -> flag bytes in (reused) shared memory
    uint8_t* flags = (uint8_t*)&As[0][0];   // 128*64 = 8KB, fits in As
#pragma unroll
    for (int j = 0; j < 4; ++j) {
        int n = colBase + tx * 4 + j;
        float scale = __fmul_rn(gam[n], rsqrtf(__fadd_rn(var[n], EPSV)));
        float mn = mean[n], bt = bet[n], bs = bias[n];
#pragma unroll
        for (int i = 0; i < 8; ++i) {
            float hf = __fadd_rn((float)(Kfull - 2 * (int)acc[i][j]), bs);
            float f  = __fadd_rn(__fmul_rn(__fsub_rn(hf, mn), scale), bt);
            flags[(ty * 8 + i) * 64 + tx * 4 + j] = (f < 0.0f) ? (uint8_t)1 : (uint8_t)0;
        }
    }
    __syncthreads();

    // Pack: 128 rows x 2 output words = 256 words, one per thread
    {
        int r = tid >> 1, cw = tid & 1;
        const uint8_t* fr = flags + r * 64 + cw * 32;
        uint32_t wbits = 0u;
#pragma unroll
        for (int i = 0; i < 32; ++i) wbits |= ((uint32_t)fr[i]) << i;
        O[(size_t)(rowBase + r) * 128 + (colBase >> 5) + cw] = wbits;
    }
}

// ---------------------------------------------------------------------------
// Layer 4 (4096 -> 10) + BN + log_softmax. One warp per row.
// ---------------------------------------------------------------------------
__global__ void final_kernel(const uint32_t* __restrict__ A, const uint32_t* __restrict__ W4,
                             const float* __restrict__ bias, const float* __restrict__ gam,
                             const float* __restrict__ bet,  const float* __restrict__ mean,
                             const float* __restrict__ var,  float* __restrict__ out) {
    int wg   = (blockIdx.x * blockDim.x + threadIdx.x) >> 5;
    int lane = threadIdx.x & 31;
    if (wg >= NROWS) return;

    uint32_t aw[4];
#pragma unroll
    for (int j = 0; j < 4; ++j) aw[j] = A[(size_t)wg * 128 + j * 32 + lane];

    float f[10];
#pragma unroll
    for (int o = 0; o < 10; ++o) {
        uint32_t c = 0u;
#pragma unroll
        for (int j = 0; j < 4; ++j) c += (uint32_t)__popc(aw[j] ^ W4[o * 128 + j * 32 + lane]);
        uint32_t tot = __reduce_add_sync(0xffffffffu, c);
        float hf    = __fadd_rn((float)(4096 - 2 * (int)tot), bias[o]);
        float scale = __fmul_rn(gam[o], rsqrtf(__fadd_rn(var[o], EPSV)));
        f[o] = __fadd_rn(__fmul_rn(__fsub_rn(hf, mean[o]), scale), bet[o]);
    }
    float mx = f[0];
#pragma unroll
    for (int o = 1; o < 10; ++o) mx = fmaxf(mx, f[o]);
    float s = 0.0f;
#pragma unroll
    for (int o = 0; o < 10; ++o) s += expf(f[o] - mx);
    float lse = logf(s);
    if (lane < 10) out[(size_t)wg * 10 + lane] = (f[lane] - mx) - lse;
}

// ---------------------------------------------------------------------------
extern "C" void kernel_launch(void* const* d_in, const int* in_sizes, int n_in,
                              void* d_out, int out_size) {
    (void)in_sizes; (void)n_in; (void)out_size;
    const float* x  = (const float*)d_in[0];
    const float* w1 = (const float*)d_in[1];
    const float* b1 = (const float*)d_in[2];
    const float* g1 = (const float*)d_in[3];
    const float* be1= (const float*)d_in[4];
    const float* m1 = (const float*)d_in[5];
    const float* v1 = (const float*)d_in[6];
    const float* w2 = (const float*)d_in[7];
    const float* b2 = (const float*)d_in[8];
    const float* g2 = (const float*)d_in[9];
    const float* be2= (const float*)d_in[10];
    const float* m2 = (const float*)d_in[11];
    const float* v2 = (const float*)d_in[12];
    const float* w3 = (const float*)d_in[13];
    const float* b3 = (const float*)d_in[14];
    const float* g3 = (const float*)d_in[15];
    const float* be3= (const float*)d_in[16];
    const float* m3 = (const float*)d_in[17];
    const float* v3 = (const float*)d_in[18];
    const float* w4 = (const float*)d_in[19];
    const float* b4 = (const float*)d_in[20];
    const float* g4 = (const float*)d_in[21];
    const float* be4= (const float*)d_in[22];
    const float* m4 = (const float*)d_in[23];
    const float* v4 = (const float*)d_in[24];
    float* out = (float*)d_out;

    uint32_t *xb, *a0, *a1, *wb1, *wb2, *wb3, *wb4;
    cudaGetSymbolAddress((void**)&xb,  g_xb);
    cudaGetSymbolAddress((void**)&a0,  g_act0);
    cudaGetSymbolAddress((void**)&a1,  g_act1);
    cudaGetSymbolAddress((void**)&wb1, g_wb1);
    cudaGetSymbolAddress((void**)&wb2, g_wb2);
    cudaGetSymbolAddress((void**)&wb3, g_wb3);
    cudaGetSymbolAddress((void**)&wb4, g_wb4);

    // Binarize input + weights (bit = value<0)
    binarize_kernel<<<(NROWS * 32) / 256, 256>>>(x,  xb,  NROWS, 24, 784);
    binarize_kernel<<<(4096  * 32) / 256, 256>>>(w1, wb1, 4096, 24, 768);
    binarize_kernel<<<(4096  * 32) / 256, 256>>>(w2, wb2, 4096, 128, 4096);
    binarize_kernel<<<(4096  * 32) / 256, 256>>>(w3, wb3, 4096, 128, 4096);
    binarize_kernel<<<2, 256>>>(w4, wb4, 10, 128, 4096);

    dim3 grid(4096 / 64, NROWS / 128);
    // L1: K=768 (24 words)
    bitgemm_kernel<24, 24><<<grid, 256>>>(xb, wb1, b1, g1, be1, m1, v1, a0, 768);
    // L2: K=4096 (128 words)
    bitgemm_kernel<128, 32><<<grid, 256>>>(a0, wb2, b2, g2, be2, m2, v2, a1, 4096);
    // L3
    bitgemm_kernel<128, 32><<<grid, 256>>>(a1, wb3, b3, g3, be3, m3, v3, a0, 4096);
    // L4 + log_softmax
    final_kernel<<<(NROWS * 32) / 256, 256>>>(a0, wb4, b4, g4, be4, m4, v4, out);
}